// round 15
// baseline (speedup 1.0000x reference)
#include <cuda_runtime.h>
#include <cuda.h>
#include <cstdint>

// AlignedLinear: y[n, o*9+d] = alpha * sum_i x[n, i*9+d] * K[r(d), i, o]
// r(d)=0 d=0; 1 d=1..3; 2 d=4..8.
//
// R15: MT=24 nodes/CTA (tile 110592 B) -> 2 CTAs/SM x 256 threads = 16
// warps/SM. 24 % 8 == 0 keeps the TMA SW128 swizzle key = node&7, a per-lane
// CONSTANT (cheap addressing, unlike MT=12). WG0 (warps 0-3) owns node rows
// 0-15; WG1 (warps 4-7) owns rows 16-23 plus 8 pad rows (24-31): pad A-reads
// are discarded, pad writeback predicated off. Word sets are disjoint -> no
// cross-WG sync; one named barrier per pass per WG. One tile per CTA (R9
// style); overlap comes from the 2 co-resident CTAs being out of phase.
// TMA in/out (view [32f][node][36seg]); B from fragment-major tf32 global
// buffer (alpha folded), prefetch depth 2. DC=5 irrep split 3+2 for regs.

#define MT        24
#define DIMT      9
#define MUL       128
#define ROWF      1152
#define TILE_BYTES (MT * ROWF * 4)      // 110592
#define SEG_STRIDE (MT * 128)           // 3072 B per seg in smem
#define NTHREADS  256
#define ALPHA_F   0.08838834764831845f  // sqrt(1/128)

#define KB_WORDS  (3 * 16 * 16 * 64)
__device__ __align__(16) uint32_t g_kbuf[KB_WORDS];

static __device__ __forceinline__ uint32_t f2tf32(float f) {
    uint32_t u;
    asm("cvt.rna.tf32.f32 %0, %1;" : "=r"(u) : "f"(f));
    return u;
}

static __device__ __forceinline__ void mma_tf32(float c[4],
    uint32_t a0, uint32_t a1, uint32_t a2, uint32_t a3,
    uint32_t b0, uint32_t b1)
{
    asm volatile(
        "mma.sync.aligned.m16n8k8.row.col.f32.tf32.tf32.f32 "
        "{%0,%1,%2,%3}, {%4,%5,%6,%7}, {%8,%9}, {%0,%1,%2,%3};"
        : "+f"(c[0]), "+f"(c[1]), "+f"(c[2]), "+f"(c[3])
        : "r"(a0), "r"(a1), "r"(a2), "r"(a3), "r"(b0), "r"(b1));
}

// ---- Prep: K[r][i][o] fp32 -> fragment-major tf32 (RNA), alpha folded ----
__global__ void prep_k_kernel(const float* __restrict__ kern)
{
    int idx = blockIdx.x * blockDim.x + threadIdx.x;
    if (idx >= KB_WORDS) return;
    int j    = idx & 1;
    int lane = (idx >> 1) & 31;
    int nt   = (idx >> 6) & 15;
    int k8   = (idx >> 10) & 15;
    int r    = idx >> 14;
    int k = k8 * 8 + (lane & 3) + 4 * j;
    int o = nt * 8 + (lane >> 2);
    g_kbuf[idx] = f2tf32(ALPHA_F * kern[(r * MUL + k) * MUL + o]);
}

// Swizzled byte offset (relative to node-row base) of word w = 9k+d.
// chunk = seg*24 + node; 24%8==0 -> key = (node&7)<<4, CONSTANT per lane.
static __device__ __forceinline__ uint32_t swz(int w, uint32_t xm) {
    return ((uint32_t)w >> 5) * (uint32_t)SEG_STRIDE
         + ((((uint32_t)w & 31u) << 2) ^ xm);
}

static __device__ __forceinline__ uint32_t lds32(uint32_t a) {
    uint32_t v;
    asm volatile("ld.shared.b32 %0, [%1];" : "=r"(v) : "r"(a));
    return v;
}
static __device__ __forceinline__ void sts32(uint32_t a, float v) {
    asm volatile("st.shared.b32 [%0], %1;" :: "r"(a), "f"(v));
}

static __device__ __forceinline__ void mbar_wait(uint32_t bar, uint32_t parity) {
    asm volatile(
        "{\n\t.reg .pred P;\n\t"
        "WL_%=:\n\t"
        "mbarrier.try_wait.parity.acquire.cta.shared::cta.b64 P, [%0], %1, 0x989680;\n\t"
        "@P bra WD_%=;\n\t"
        "bra WL_%=;\n\t"
        "WD_%=:\n\t}"
        :: "r"(bar), "r"(parity) : "memory");
}

// One irrep pass for ONE warpgroup. rowb already includes the WG's m0 row
// offset. hi_valid: rows m0+g+8 live (true for WG0; false for WG1 = pad).
template<int R, int D0, int DC, int KU>
static __device__ __forceinline__ void process_group(
    uint32_t rowb, uint32_t xm, int tg, int lane, int wwg, int barid,
    bool hi_valid)
{
    const uint2* kb = reinterpret_cast<const uint2*>(g_kbuf)
                    + ((size_t)R * 256 + wwg * 4) * 32 + lane;

    float c[DC][4][4];
    #pragma unroll
    for (int dd = 0; dd < DC; ++dd)
        #pragma unroll
        for (int nt = 0; nt < 4; ++nt)
            #pragma unroll
            for (int i = 0; i < 4; ++i) c[dd][nt][i] = 0.f;

    uint2 buf[2][4];
    #pragma unroll
    for (int nt = 0; nt < 4; ++nt) buf[0][nt] = __ldg(kb + nt * 32);
    #pragma unroll
    for (int nt = 0; nt < 4; ++nt) buf[1][nt] = __ldg(kb + 512 + nt * 32);

    #pragma unroll KU
    for (int k8 = 0; k8 < 16; ++k8) {
        uint2 cur[4];
        #pragma unroll
        for (int nt = 0; nt < 4; ++nt) cur[nt] = buf[k8 & 1][nt];
        if (k8 < 14) {
            const uint2* kbn = kb + (k8 + 2) * 512;
            #pragma unroll
            for (int nt = 0; nt < 4; ++nt)
                buf[k8 & 1][nt] = __ldg(kbn + nt * 32);
        }
        #pragma unroll
        for (int dd = 0; dd < DC; ++dd) {
            const int w0 = 72 * k8 + 9 * tg + (D0 + dd);
            const uint32_t o0 = rowb + swz(w0,      xm);
            const uint32_t o1 = rowb + swz(w0 + 36, xm);
            uint32_t a0 = lds32(o0);
            uint32_t a1 = lds32(o0 + 1024);   // +8 rows (pad for WG1)
            uint32_t a2 = lds32(o1);
            uint32_t a3 = lds32(o1 + 1024);
            #pragma unroll
            for (int nt = 0; nt < 4; ++nt)
                mma_tf32(c[dd][nt], a0, a1, a2, a3, cur[nt].x, cur[nt].y);
        }
    }

    // This WG done reading its rows' d-words of this pass.
    asm volatile("bar.sync %0, 128;" :: "r"(barid) : "memory");

    #pragma unroll
    for (int dd = 0; dd < DC; ++dd) {
        #pragma unroll
        for (int nt = 0; nt < 4; ++nt) {
            const int o = wwg * 32 + nt * 8 + 2 * tg;
            const int w = o * 9 + (D0 + dd);
            const uint32_t p0 = rowb + swz(w,     xm);
            const uint32_t p1 = rowb + swz(w + 9, xm);
            sts32(p0, c[dd][nt][0]);
            sts32(p1, c[dd][nt][1]);
            if (hi_valid) {
                sts32(p0 + 1024, c[dd][nt][2]);
                sts32(p1 + 1024, c[dd][nt][3]);
            }
        }
    }
}

__global__ void __launch_bounds__(NTHREADS, 2)
aligned_linear_m24(const __grid_constant__ CUtensorMap tmx,
                   const __grid_constant__ CUtensorMap tmy)
{
    extern __shared__ uint32_t dyn[];
    const uint32_t raw   = (uint32_t)__cvta_generic_to_shared(dyn);
    const uint32_t tbase = (raw + 1023u) & ~1023u;   // SW128: 1KB align
    // pad-row reads overrun the tile by <2KB; bar sits after that slack.
    const uint32_t bar   = tbase + TILE_BYTES + 2048;

    const int tid  = threadIdx.x;
    const int lane = tid & 31;
    const int warp = tid >> 5;
    const int wg   = warp >> 2;        // 0: rows 0-15, 1: rows 16-23 (+pad)
    const int wwg  = warp & 3;
    const int g    = lane >> 2;
    const int tg   = lane & 3;
    const int node0 = blockIdx.x * MT;

    const uint32_t xm   = (uint32_t)g << 4;               // (g&7)<<4, const
    const uint32_t rowb = tbase + (uint32_t)(wg * 16 + g) * 128u;
    const bool hi_valid = (wg == 0);
    const int  barid    = 1 + wg;

    if (tid == 0)
        asm volatile("mbarrier.init.shared.b64 [%0], 1;" :: "r"(bar));
    __syncthreads();

    if (tid == 0) {
        asm volatile("mbarrier.arrive.expect_tx.shared.b64 _, [%0], %1;"
                     :: "r"(bar), "r"(TILE_BYTES));
        asm volatile(
            "cp.async.bulk.tensor.3d.shared::cta.global.tile"
            ".mbarrier::complete_tx::bytes [%0], [%1, {%2, %3, %4}], [%5];"
            :: "r"(tbase), "l"(&tmx),
               "r"(0), "r"(node0), "r"(0), "r"(bar) : "memory");
    }
    mbar_wait(bar, 0u);

    process_group<0, 0, 1, 2>(rowb, xm, tg, lane, wwg, barid, hi_valid);
    process_group<1, 1, 3, 1>(rowb, xm, tg, lane, wwg, barid, hi_valid);
    process_group<2, 4, 3, 1>(rowb, xm, tg, lane, wwg, barid, hi_valid);
    process_group<2, 7, 2, 1>(rowb, xm, tg, lane, wwg, barid, hi_valid);

    __syncthreads();   // both WGs' writebacks visible

    if (tid == 0) {
        asm volatile("fence.proxy.async;" ::: "memory");
        asm volatile(
            "cp.async.bulk.tensor.3d.global.shared::cta.tile.bulk_group "
            "[%0, {%1, %2, %3}], [%4];"
            :: "l"(&tmy), "r"(0), "r"(node0), "r"(0), "r"(tbase) : "memory");
        asm volatile("cp.async.bulk.commit_group;");
        asm volatile("cp.async.bulk.wait_group 0;");
    }
}

extern "C" void kernel_launch(void* const* d_in, const int* in_sizes, int n_in,
                              void* d_out, int out_size)
{
    const float* x = (const float*)d_in[0];
    const float* k = (const float*)d_in[1];
    float* y = (float*)d_out;
    int n_nodes = in_sizes[0] / ROWF;
    int ntiles  = (n_nodes + MT - 1) / MT;

    prep_k_kernel<<<(KB_WORDS + 255) / 256, 256>>>(k);

    typedef CUresult (*enc_t)(CUtensorMap*, CUtensorMapDataType, cuuint32_t,
                              void*, const cuuint64_t*, const cuuint64_t*,
                              const cuuint32_t*, const cuuint32_t*,
                              CUtensorMapInterleave, CUtensorMapSwizzle,
                              CUtensorMapL2promotion, CUtensorMapFloatOOBfill);
    enc_t enc = nullptr;
    {
        void* p = nullptr;
        cudaDriverEntryPointQueryResult qr;
        cudaGetDriverEntryPointByVersion("cuTensorMapEncodeTiled", &p, 12000,
                                         cudaEnableDefault, &qr);
        enc = (enc_t)p;
    }

    // View: [32 floats][node][36 segs]; box [32, 24, 36]; SW128.
    // Loads zero-fill OOB nodes; stores clip (50000 % 24 != 0 safe).
    cuuint64_t dims[3]    = {32, (cuuint64_t)n_nodes, 36};
    cuuint64_t strides[2] = {(cuuint64_t)ROWF * 4, 128};
    cuuint32_t box[3]     = {32, MT, 36};
    cuuint32_t es[3]      = {1, 1, 1};

    CUtensorMap tmx, tmy;
    enc(&tmx, CU_TENSOR_MAP_DATA_TYPE_FLOAT32, 3, (void*)x,
        dims, strides, box, es,
        CU_TENSOR_MAP_INTERLEAVE_NONE, CU_TENSOR_MAP_SWIZZLE_128B,
        CU_TENSOR_MAP_L2_PROMOTION_L2_128B, CU_TENSOR_MAP_FLOAT_OOB_FILL_NONE);
    enc(&tmy, CU_TENSOR_MAP_DATA_TYPE_FLOAT32, 3, (void*)y,
        dims, strides, box, es,
        CU_TENSOR_MAP_INTERLEAVE_NONE, CU_TENSOR_MAP_SWIZZLE_128B,
        CU_TENSOR_MAP_L2_PROMOTION_L2_128B, CU_TENSOR_MAP_FLOAT_OOB_FILL_NONE);

    // tile + 1KB align slack + 2KB pad-row read slack + mbar
    size_t smem = TILE_BYTES + 1024 + 2048 + 16;
    cudaFuncSetAttribute(aligned_linear_m24,
                         cudaFuncAttributeMaxDynamicSharedMemorySize,
                         (int)smem);

    aligned_linear_m24<<<ntiles, NTHREADS, smem>>>(tmx, tmy);
}

// round 16
// speedup vs baseline: 1.4669x; 1.4669x over previous
#include <cuda_runtime.h>
#include <cuda.h>
#include <cstdint>

// AlignedLinear: y[n, o*9+d] = alpha * sum_i x[n, i*9+d] * K[r(d), i, o]
// r(d)=0 d=0; 1 d=1..3; 2 d=4..8.
//
// R16: MT=8 nodes/CTA, d-PAIRED m16 fragments. The m16n8k8 A fragment's
// rows 8-15 (a1/a3) are free lane-local loads, so one fragment packs TWO
// dims of the SAME irrep: rows 0-7 = [8 nodes x da], rows 8-15 = [same
// nodes x db] (B is shared within an irrep). Pairs (d1,d2),(d4,d5),(d6,d7);
// halves (d0),(d3),(d8) with a1:=a0 (no extra LDS, hi rows discarded).
// Tile 36864 B -> 6 CTAs/SM x 4 warps = 24 warps/SM (occ 37.5%); phase
// overlap from 6 independent CTAs. TMA in/out (SW128, view
// [32f][node][36seg], chunk=8seg+node -> key=node&7, per-lane CONSTANT).
// B from fragment-major tf32 global buffer (alpha folded), prefetch depth 2.

#define MT        8
#define DIMT      9
#define MUL       128
#define ROWF      1152
#define TILE_BYTES (MT * ROWF * 4)      // 36864
#define SEG_STRIDE (MT * 128)           // 1024 B per seg in smem
#define NTHREADS  128
#define ALPHA_F   0.08838834764831845f  // sqrt(1/128)

#define KB_WORDS  (3 * 16 * 16 * 64)
__device__ __align__(16) uint32_t g_kbuf[KB_WORDS];

static __device__ __forceinline__ uint32_t f2tf32(float f) {
    uint32_t u;
    asm("cvt.rna.tf32.f32 %0, %1;" : "=r"(u) : "f"(f));
    return u;
}

static __device__ __forceinline__ void mma_tf32(float c[4],
    uint32_t a0, uint32_t a1, uint32_t a2, uint32_t a3,
    uint32_t b0, uint32_t b1)
{
    asm volatile(
        "mma.sync.aligned.m16n8k8.row.col.f32.tf32.tf32.f32 "
        "{%0,%1,%2,%3}, {%4,%5,%6,%7}, {%8,%9}, {%0,%1,%2,%3};"
        : "+f"(c[0]), "+f"(c[1]), "+f"(c[2]), "+f"(c[3])
        : "r"(a0), "r"(a1), "r"(a2), "r"(a3), "r"(b0), "r"(b1));
}

// ---- Prep: K[r][i][o] fp32 -> fragment-major tf32 (RNA), alpha folded ----
__global__ void prep_k_kernel(const float* __restrict__ kern)
{
    int idx = blockIdx.x * blockDim.x + threadIdx.x;
    if (idx >= KB_WORDS) return;
    int j    = idx & 1;
    int lane = (idx >> 1) & 31;
    int nt   = (idx >> 6) & 15;
    int k8   = (idx >> 10) & 15;
    int r    = idx >> 14;
    int k = k8 * 8 + (lane & 3) + 4 * j;
    int o = nt * 8 + (lane >> 2);
    g_kbuf[idx] = f2tf32(ALPHA_F * kern[(r * MUL + k) * MUL + o]);
}

// Swizzled byte offset (relative to node-row base) of word w = 9k+d.
// chunk = seg*8 + node -> key = (node&7)<<4 = xm, per-lane constant.
static __device__ __forceinline__ uint32_t swz(int w, uint32_t xm) {
    return ((uint32_t)w >> 5) * (uint32_t)SEG_STRIDE
         + ((((uint32_t)w & 31u) << 2) ^ xm);
}

static __device__ __forceinline__ uint32_t lds32(uint32_t a) {
    uint32_t v;
    asm volatile("ld.shared.b32 %0, [%1];" : "=r"(v) : "r"(a));
    return v;
}
static __device__ __forceinline__ void sts32(uint32_t a, float v) {
    asm volatile("st.shared.b32 [%0], %1;" :: "r"(a), "f"(v));
}

static __device__ __forceinline__ void mbar_wait(uint32_t bar, uint32_t parity) {
    asm volatile(
        "{\n\t.reg .pred P;\n\t"
        "WL_%=:\n\t"
        "mbarrier.try_wait.parity.acquire.cta.shared::cta.b64 P, [%0], %1, 0x989680;\n\t"
        "@P bra WD_%=;\n\t"
        "bra WL_%=;\n\t"
        "WD_%=:\n\t}"
        :: "r"(bar), "r"(parity) : "memory");
}

// One pass over K for irrep R with up to two fragments:
//   F0 = (DA0, DB0), F1 = (DA1, DB1); DB=-1 -> half fragment (hi discarded),
//   DA1=-1 -> no second fragment. All fragments share this pass's B.
template<int R, int DA0, int DB0, int DA1, int DB1>
static __device__ __forceinline__ void process_pass(
    uint32_t rowb, uint32_t xm, int tg, int lane, int warp)
{
    const uint2* kb = reinterpret_cast<const uint2*>(g_kbuf)
                    + ((size_t)R * 256 + warp * 4) * 32 + lane;
    constexpr int NF = (DA1 >= 0) ? 2 : 1;

    float c[NF][2][4][4];   // [frag][??] -> use [frag] x [nt]: c[f][0]=lo pair
    // Layout: c[f][0][nt][i] unused split; keep simple: c2[f][nt][4]
    float acc[NF][4][4];
    #pragma unroll
    for (int f = 0; f < NF; ++f)
        #pragma unroll
        for (int nt = 0; nt < 4; ++nt)
            #pragma unroll
            for (int i = 0; i < 4; ++i) acc[f][nt][i] = 0.f;
    (void)c;

    uint2 buf[2][4];
    #pragma unroll
    for (int nt = 0; nt < 4; ++nt) buf[0][nt] = __ldg(kb + nt * 32);
    #pragma unroll
    for (int nt = 0; nt < 4; ++nt) buf[1][nt] = __ldg(kb + 512 + nt * 32);

    #pragma unroll 2
    for (int k8 = 0; k8 < 16; ++k8) {
        uint2 cur[4];
        #pragma unroll
        for (int nt = 0; nt < 4; ++nt) cur[nt] = buf[k8 & 1][nt];
        if (k8 < 14) {
            const uint2* kbn = kb + (k8 + 2) * 512;
            #pragma unroll
            for (int nt = 0; nt < 4; ++nt)
                buf[k8 & 1][nt] = __ldg(kbn + nt * 32);
        }
        const int wbase = 72 * k8 + 9 * tg;

        #pragma unroll
        for (int f = 0; f < NF; ++f) {
            const int da = (f == 0) ? DA0 : DA1;
            const int db = (f == 0) ? DB0 : DB1;
            const int wa = wbase + da;
            uint32_t a0 = lds32(rowb + swz(wa,      xm));
            uint32_t a2 = lds32(rowb + swz(wa + 36, xm));
            uint32_t a1 = a0, a3 = a2;
            if (db >= 0) {
                const int wb = wbase + db;
                a1 = lds32(rowb + swz(wb,      xm));
                a3 = lds32(rowb + swz(wb + 36, xm));
            }
            #pragma unroll
            for (int nt = 0; nt < 4; ++nt)
                mma_tf32(acc[f][nt], a0, a1, a2, a3, cur[nt].x, cur[nt].y);
        }
    }

    __syncthreads();   // all warps done reading this pass's d-words

    // Writeback: rows 0-7 -> (node g, da); rows 8-15 -> (node g, db).
    #pragma unroll
    for (int f = 0; f < NF; ++f) {
        const int da = (f == 0) ? DA0 : DA1;
        const int db = (f == 0) ? DB0 : DB1;
        #pragma unroll
        for (int nt = 0; nt < 4; ++nt) {
            const int o = warp * 32 + nt * 8 + 2 * tg;
            sts32(rowb + swz(o * 9 + da,       xm), acc[f][nt][0]);
            sts32(rowb + swz((o + 1) * 9 + da, xm), acc[f][nt][1]);
            if (db >= 0) {
                sts32(rowb + swz(o * 9 + db,       xm), acc[f][nt][2]);
                sts32(rowb + swz((o + 1) * 9 + db, xm), acc[f][nt][3]);
            }
        }
    }
}

__global__ void __launch_bounds__(NTHREADS, 6)
aligned_linear_pair(const __grid_constant__ CUtensorMap tmx,
                    const __grid_constant__ CUtensorMap tmy)
{
    extern __shared__ uint32_t dyn[];
    const uint32_t raw   = (uint32_t)__cvta_generic_to_shared(dyn);
    const uint32_t tbase = (raw + 1023u) & ~1023u;   // SW128: 1KB align
    const uint32_t bar   = tbase + TILE_BYTES;

    const int tid  = threadIdx.x;
    const int lane = tid & 31;
    const int warp = tid >> 5;
    const int g    = lane >> 2;
    const int tg   = lane & 3;
    const int node0 = blockIdx.x * MT;

    const uint32_t xm   = (uint32_t)g << 4;      // swizzle key, constant
    const uint32_t rowb = tbase + (uint32_t)g * 128u;

    if (tid == 0)
        asm volatile("mbarrier.init.shared.b64 [%0], 1;" :: "r"(bar));
    __syncthreads();

    if (tid == 0) {
        asm volatile("mbarrier.arrive.expect_tx.shared.b64 _, [%0], %1;"
                     :: "r"(bar), "r"(TILE_BYTES));
        asm volatile(
            "cp.async.bulk.tensor.3d.shared::cta.global.tile"
            ".mbarrier::complete_tx::bytes [%0], [%1, {%2, %3, %4}], [%5];"
            :: "r"(tbase), "l"(&tmx),
               "r"(0), "r"(node0), "r"(0), "r"(bar) : "memory");
    }
    mbar_wait(bar, 0u);

    process_pass<0, 0, -1, -1, -1>(rowb, xm, tg, lane, warp);  // d0
    process_pass<1, 1,  2,  3, -1>(rowb, xm, tg, lane, warp);  // (d1,d2),(d3)
    process_pass<2, 4,  5,  6,  7>(rowb, xm, tg, lane, warp);  // (d4,d5),(d6,d7)
    process_pass<2, 8, -1, -1, -1>(rowb, xm, tg, lane, warp);  // d8

    __syncthreads();   // all writebacks visible

    if (tid == 0) {
        asm volatile("fence.proxy.async;" ::: "memory");
        asm volatile(
            "cp.async.bulk.tensor.3d.global.shared::cta.tile.bulk_group "
            "[%0, {%1, %2, %3}], [%4];"
            :: "l"(&tmy), "r"(0), "r"(node0), "r"(0), "r"(tbase) : "memory");
        asm volatile("cp.async.bulk.commit_group;");
        asm volatile("cp.async.bulk.wait_group 0;");
    }
}

extern "C" void kernel_launch(void* const* d_in, const int* in_sizes, int n_in,
                              void* d_out, int out_size)
{
    const float* x = (const float*)d_in[0];
    const float* k = (const float*)d_in[1];
    float* y = (float*)d_out;
    int n_nodes = in_sizes[0] / ROWF;
    int ntiles  = (n_nodes + MT - 1) / MT;

    prep_k_kernel<<<(KB_WORDS + 255) / 256, 256>>>(k);

    typedef CUresult (*enc_t)(CUtensorMap*, CUtensorMapDataType, cuuint32_t,
                              void*, const cuuint64_t*, const cuuint64_t*,
                              const cuuint32_t*, const cuuint32_t*,
                              CUtensorMapInterleave, CUtensorMapSwizzle,
                              CUtensorMapL2promotion, CUtensorMapFloatOOBfill);
    enc_t enc = nullptr;
    {
        void* p = nullptr;
        cudaDriverEntryPointQueryResult qr;
        cudaGetDriverEntryPointByVersion("cuTensorMapEncodeTiled", &p, 12000,
                                         cudaEnableDefault, &qr);
        enc = (enc_t)p;
    }

    // View: [32 floats][node][36 segs]; box [32, 8, 36]; SW128.
    cuuint64_t dims[3]    = {32, (cuuint64_t)n_nodes, 36};
    cuuint64_t strides[2] = {(cuuint64_t)ROWF * 4, 128};
    cuuint32_t box[3]     = {32, MT, 36};
    cuuint32_t es[3]      = {1, 1, 1};

    CUtensorMap tmx, tmy;
    enc(&tmx, CU_TENSOR_MAP_DATA_TYPE_FLOAT32, 3, (void*)x,
        dims, strides, box, es,
        CU_TENSOR_MAP_INTERLEAVE_NONE, CU_TENSOR_MAP_SWIZZLE_128B,
        CU_TENSOR_MAP_L2_PROMOTION_L2_128B, CU_TENSOR_MAP_FLOAT_OOB_FILL_NONE);
    enc(&tmy, CU_TENSOR_MAP_DATA_TYPE_FLOAT32, 3, (void*)y,
        dims, strides, box, es,
        CU_TENSOR_MAP_INTERLEAVE_NONE, CU_TENSOR_MAP_SWIZZLE_128B,
        CU_TENSOR_MAP_L2_PROMOTION_L2_128B, CU_TENSOR_MAP_FLOAT_OOB_FILL_NONE);

    size_t smem = TILE_BYTES + 1024 + 16;   // tile + align slack + mbar
    cudaFuncSetAttribute(aligned_linear_pair,
                         cudaFuncAttributeMaxDynamicSharedMemorySize,
                         (int)smem);

    aligned_linear_pair<<<ntiles, NTHREADS, smem>>>(tmx, tmy);
}